// round 6
// baseline (speedup 1.0000x reference)
#include <cuda_runtime.h>
#include <cuda_bf16.h>
#include <math.h>
#include <stdint.h>

#define B_    512
#define E_    1024
#define ML_   50
#define V_    50000
#define G4E_  (4*E_)
#define NPADV 50048          // V padded to multiple of 128
#define KP3   (3*E_)         // 3072: logits K after x3 expansion
#define KG    2048           // gates base K ([words|ctx] vs [w_ih|w_hh])
#define KG3   (3*KG)         // 6144

// ---------------- scratch (__device__ globals; allocation-free rule) --------
__device__ float g_words[B_*E_];
__device__ float g_ctx[B_*E_];
__device__ float g_gates[(long long)B_*G4E_];
__device__ int   g_pad_byte_mode;

__device__ __nv_bfloat16 g_wp3[(long long)NPADV*KP3];  // [Bh|Bh|Bl]
__device__ __nv_bfloat16 g_wg3[(long long)G4E_*KG3];   // [Bh|Bh|Bl]
__device__ __nv_bfloat16 g_ag3[B_*KG3];                // [Ah|Al|Ah]
__device__ __nv_bfloat16 g_h3[B_*KP3];                 // [Ah|Al|Ah]

// ---------------- PTX helpers (arch-stable only: sm_80-era) -----------------
__device__ __forceinline__ uint32_t smem_u32(const void* p) {
    uint32_t a;
    asm("{ .reg .u64 t; cvta.to.shared.u64 t, %1; cvt.u32.u64 %0, t; }" : "=r"(a) : "l"(p));
    return a;
}
#define CP_ASYNC16(dst, src) \
    asm volatile("cp.async.cg.shared.global [%0], [%1], 16;" :: "r"(dst), "l"(src) : "memory")
#define CP_COMMIT() asm volatile("cp.async.commit_group;" ::: "memory")
#define CP_WAIT1()  asm volatile("cp.async.wait_group 1;" ::: "memory")
#define CP_WAIT0()  asm volatile("cp.async.wait_group 0;" ::: "memory")

__device__ __forceinline__ void ldsm_x4(uint32_t addr, uint32_t& r0, uint32_t& r1,
                                        uint32_t& r2, uint32_t& r3) {
    asm volatile("ldmatrix.sync.aligned.m8n8.x4.shared.b16 {%0,%1,%2,%3}, [%4];"
                 : "=r"(r0), "=r"(r1), "=r"(r2), "=r"(r3) : "r"(addr));
}
__device__ __forceinline__ void mma16816(float* c, const uint32_t* a, const uint32_t* b) {
    asm volatile("mma.sync.aligned.m16n8k16.row.col.f32.bf16.bf16.f32 "
                 "{%0,%1,%2,%3}, {%4,%5,%6,%7}, {%8,%9}, {%0,%1,%2,%3};"
                 : "+f"(c[0]), "+f"(c[1]), "+f"(c[2]), "+f"(c[3])
                 : "r"(a[0]), "r"(a[1]), "r"(a[2]), "r"(a[3]), "r"(b[0]), "r"(b[1]));
}
__device__ __forceinline__ uint32_t swz128(uint32_t o) { return o ^ ((o >> 3) & 0x70); }

// ---------------------------------------------------------------------------
// pad dtype detect / gather / attention (unchanged from round 2 pass)
// ---------------------------------------------------------------------------
__global__ void detect_pad_kernel(const unsigned char* __restrict__ pad) {
    __shared__ int s_gt1, s_off4;
    if (threadIdx.x == 0) { s_gt1 = 0; s_off4 = 0; }
    __syncthreads();
    for (int i = threadIdx.x; i < B_*ML_; i += blockDim.x) {
        unsigned char v = pad[i];
        if (v > 1) atomicOr(&s_gt1, 1);
        if (v != 0 && (i & 3) != 0) atomicOr(&s_off4, 1);
    }
    __syncthreads();
    if (threadIdx.x == 0)
        g_pad_byte_mode = (s_gt1 == 0 && s_off4 != 0) ? 1 : 0;
}

__global__ void gather_words_kernel(const int* __restrict__ tgt,
                                    const float* __restrict__ emb) {
    int idx = blockIdx.x * blockDim.x + threadIdx.x;
    if (idx >= B_*E_) return;
    int b = idx >> 10, e = idx & (E_ - 1);
    g_words[idx] = emb[(long long)tgt[b] * E_ + e];
}

__global__ void attn_kernel(const float* __restrict__ enc,
                            const float* __restrict__ h0,
                            const void* __restrict__ pad_raw) {
    int b = blockIdx.x;
    __shared__ float sh_h[E_];
    __shared__ float sh_w[ML_];
    int tid = threadIdx.x;
    for (int i = tid; i < E_; i += 256) sh_h[i] = h0[(long long)b*E_ + i];
    __syncthreads();
    int w = tid >> 5, lane = tid & 31;
    for (int l = w; l < ML_; l += 8) {
        const float* row = enc + ((long long)b*ML_ + l) * E_;
        float s = 0.f;
        for (int e = lane; e < E_; e += 32) s += row[e] * sh_h[e];
        #pragma unroll
        for (int o = 16; o > 0; o >>= 1) s += __shfl_down_sync(0xffffffffu, s, o);
        if (lane == 0) sh_w[l] = s;
    }
    __syncthreads();
    if (tid == 0) {
        int bm = g_pad_byte_mode;
        const unsigned char* p8 = (const unsigned char*)pad_raw;
        const unsigned int*  pw = (const unsigned int*)pad_raw;
        float mx = -1e30f;
        for (int l = 0; l < ML_; l++) mx = fmaxf(mx, sh_w[l]);
        float sum = 0.f;
        for (int l = 0; l < ML_; l++) {
            bool masked = bm ? (p8[b*ML_ + l] != 0) : (pw[b*ML_ + l] != 0u);
            float v = masked ? 0.f : __expf(sh_w[l] - mx);
            sh_w[l] = v; sum += v;
        }
        float inv = 1.f / sum;
        for (int l = 0; l < ML_; l++) sh_w[l] *= inv;
    }
    __syncthreads();
    for (int e = tid; e < E_; e += 256) {
        const float* base = enc + (long long)b*ML_*E_ + e;
        float acc = 0.f;
        #pragma unroll 10
        for (int l = 0; l < ML_; l++) acc += sh_w[l] * base[(long long)l*E_];
        g_ctx[(long long)b*E_ + e] = acc;
    }
}

// ---------------------------------------------------------------------------
// fp32 -> bf16 hi/lo split, x3-concatenated-K layouts.
// Weights  (B side): [hi | hi | lo]
// Activs   (A side): [hi | lo | hi]
// ---------------------------------------------------------------------------
__device__ __forceinline__ void split1(float x, __nv_bfloat16& h, __nv_bfloat16& l) {
    h = __float2bfloat16(x);
    l = __float2bfloat16(x - __bfloat162float(h));
}

__global__ void conv_wproj_kernel(const float* __restrict__ src) {
    long long t = (long long)blockIdx.x * blockDim.x + threadIdx.x;
    long long total = (long long)NPADV * (E_/4);
    if (t >= total) return;
    int row = (int)(t / (E_/4));
    int k0  = (int)(t % (E_/4)) * 4;
    float4 v = (row < V_) ? *(const float4*)(src + (long long)row*E_ + k0)
                          : make_float4(0.f,0.f,0.f,0.f);
    long long o = (long long)row * KP3 + k0;
    #pragma unroll
    for (int q = 0; q < 4; q++) {
        float x = (&v.x)[q];
        __nv_bfloat16 h, l; split1(x, h, l);
        g_wp3[o + q]          = h;
        g_wp3[o + E_ + q]     = h;
        g_wp3[o + 2*E_ + q]   = l;
    }
}

__global__ void conv_wgate_kernel(const float* __restrict__ w_ih,
                                  const float* __restrict__ w_hh) {
    long long t = (long long)blockIdx.x * blockDim.x + threadIdx.x;
    long long total = (long long)G4E_ * (KG/4);
    if (t >= total) return;
    int row = (int)(t / (KG/4));
    int k0  = (int)(t % (KG/4)) * 4;
    const float* s = (k0 < E_) ? (w_ih + (long long)row*E_ + k0)
                               : (w_hh + (long long)row*E_ + (k0 - E_));
    float4 v = *(const float4*)s;
    long long o = (long long)row * KG3 + k0;
    #pragma unroll
    for (int q = 0; q < 4; q++) {
        float x = (&v.x)[q];
        __nv_bfloat16 h, l; split1(x, h, l);
        g_wg3[o + q]          = h;
        g_wg3[o + KG + q]     = h;
        g_wg3[o + 2*KG + q]   = l;
    }
}

__global__ void conv_agate_kernel() {
    int t = blockIdx.x * blockDim.x + threadIdx.x;
    int total = B_ * (KG/4);
    if (t >= total) return;
    int row = t / (KG/4);
    int k0  = (t % (KG/4)) * 4;
    const float* s = (k0 < E_) ? (g_words + row*E_ + k0) : (g_ctx + row*E_ + (k0 - E_));
    float4 v = *(const float4*)s;
    long long o = (long long)row * KG3 + k0;
    #pragma unroll
    for (int q = 0; q < 4; q++) {
        float x = (&v.x)[q];
        __nv_bfloat16 h, l; split1(x, h, l);
        g_ag3[o + q]          = h;
        g_ag3[o + KG + q]     = l;
        g_ag3[o + 2*KG + q]   = h;
    }
}

__global__ void conv_h_kernel(const float* __restrict__ hsrc) {
    int t = blockIdx.x * blockDim.x + threadIdx.x;
    int total = B_ * (E_/4);
    if (t >= total) return;
    int row = t / (E_/4);
    int k0  = (t % (E_/4)) * 4;
    float4 v = *(const float4*)(hsrc + row*E_ + k0);
    long long o = (long long)row * KP3 + k0;
    #pragma unroll
    for (int q = 0; q < 4; q++) {
        float x = (&v.x)[q];
        __nv_bfloat16 h, l; split1(x, h, l);
        g_h3[o + q]          = h;
        g_h3[o + E_ + q]     = l;
        g_h3[o + 2*E_ + q]   = h;
    }
}

// ---------------------------------------------------------------------------
// bf16 GEMM via mma.sync: C[M,N] = A[M,K3] * B[N,K3]^T (+bias)
// CTA 128x128, K-chunk 64, 3-stage cp.async pipeline, SW128 smem, ldmatrix.
// 8 warps = 4(m) x 2(n); warp tile 32x64 = 2x8 of m16n8.
// M, Npad multiples of 128; K3 multiple of 64. Stores masked to Nreal.
// ---------------------------------------------------------------------------
#define TILE_B  16384              // 128 rows x 128 bytes
#define STAGE_B (2*TILE_B)         // A tile + B tile
#define NSTAGE  3
#define GEMM_SMEM (NSTAGE*STAGE_B)

__global__ void __launch_bounds__(256, 2) gemm_bf16_mma(
    const __nv_bfloat16* __restrict__ A3, const __nv_bfloat16* __restrict__ B3,
    float* __restrict__ C, const float* __restrict__ bias,
    int K3, int Nreal)
{
    extern __shared__ char smem_raw[];
    const uint32_t smem = smem_u32(smem_raw);

    const int tid = threadIdx.x;
    const int wid = tid >> 5, lane = tid & 31;
    const int wm = wid & 3, wn = wid >> 2;
    const int m0 = blockIdx.y * 128, n0 = blockIdx.x * 128;
    const int nch = K3 >> 6;

    const __nv_bfloat16* Abase = A3 + (long long)m0 * K3;
    const __nv_bfloat16* Bbase = B3 + (long long)n0 * K3;

    // per-thread cp.async slots: 8 ops, op = tid*8..tid*8+7 over 2048
    // op: tile = op>>10, row = (op>>3)&127, c = op&7
    auto issue_stage = [&](int stage, int chunk) {
        int kc = chunk * 64;
        uint32_t sbase = smem + stage * STAGE_B;
        #pragma unroll
        for (int j = 0; j < 8; j++) {
            int op = tid * 8 + j;
            int tile = op >> 10;
            int row = (op >> 3) & 127;
            int c = op & 7;
            const __nv_bfloat16* src = (tile ? Bbase : Abase) + (long long)row * K3 + kc + c * 8;
            uint32_t dst = sbase + tile * TILE_B + swz128((uint32_t)(row * 128 + c * 16));
            CP_ASYNC16(dst, src);
        }
        CP_COMMIT();
    };

    float acc[2][8][4];
    #pragma unroll
    for (int mt = 0; mt < 2; mt++)
        #pragma unroll
        for (int nt = 0; nt < 8; nt++)
            #pragma unroll
            for (int q = 0; q < 4; q++) acc[mt][nt][q] = 0.f;

    issue_stage(0, 0);
    if (nch > 1) issue_stage(1, 1); else CP_COMMIT();

    // precompute per-lane ldmatrix row/chunk components
    const int a_row_in = lane & 15;            // 0..15
    const int a_chunk  = lane >> 4;            // 0 or 1
    const int b_row_in = (lane & 7) + ((lane & 16) ? 8 : 0);
    const int b_chunk  = (lane >> 3) & 1;

    for (int i = 0; i < nch; i++) {
        CP_WAIT1();
        __syncthreads();
        if (i + 2 < nch) issue_stage((i + 2) % NSTAGE, i + 2);
        else CP_COMMIT();

        uint32_t sbase = smem + (i % NSTAGE) * STAGE_B;
        uint32_t As = sbase, Bs = sbase + TILE_B;

        #pragma unroll
        for (int ks = 0; ks < 4; ks++) {
            uint32_t a[2][4];
            #pragma unroll
            for (int mt = 0; mt < 2; mt++) {
                int row = wm * 32 + mt * 16 + a_row_in;
                int ch  = ks * 2 + a_chunk;
                uint32_t addr = As + swz128((uint32_t)(row * 128 + ch * 16));
                ldsm_x4(addr, a[mt][0], a[mt][1], a[mt][2], a[mt][3]);
            }
            uint32_t b[8][2];
            #pragma unroll
            for (int np = 0; np < 4; np++) {
                int row = wn * 64 + np * 16 + b_row_in;
                int ch  = ks * 2 + b_chunk;
                uint32_t addr = Bs + swz128((uint32_t)(row * 128 + ch * 16));
                ldsm_x4(addr, b[np*2][0], b[np*2][1], b[np*2+1][0], b[np*2+1][1]);
            }
            #pragma unroll
            for (int mt = 0; mt < 2; mt++)
                #pragma unroll
                for (int nt = 0; nt < 8; nt++)
                    mma16816(acc[mt][nt], a[mt], b[nt]);
        }
        __syncthreads();
    }
    CP_WAIT0();

    // epilogue: c0,c1 -> (row, col..col+1); c2,c3 -> (row+8, ...)
    #pragma unroll
    for (int mt = 0; mt < 2; mt++) {
        int r0g = m0 + wm * 32 + mt * 16 + (lane >> 2);
        #pragma unroll
        for (int nt = 0; nt < 8; nt++) {
            int col = n0 + wn * 64 + nt * 8 + (lane & 3) * 2;
            if (col >= Nreal) continue;
            float bx = 0.f, by = 0.f;
            if (bias) { bx = bias[col]; by = bias[col + 1]; }
            float2 v0 = make_float2(acc[mt][nt][0] + bx, acc[mt][nt][1] + by);
            float2 v1 = make_float2(acc[mt][nt][2] + bx, acc[mt][nt][3] + by);
            *(float2*)(C + (long long)r0g * Nreal + col) = v0;
            *(float2*)(C + (long long)(r0g + 8) * Nreal + col) = v1;
        }
    }
}

// ---------------------------------------------------------------------------
// LSTM elementwise
// ---------------------------------------------------------------------------
__global__ void lstm_kernel(const float* __restrict__ b_ih,
                            const float* __restrict__ b_hh,
                            float* __restrict__ h_out,
                            float* __restrict__ c_out) {
    int idx = blockIdx.x * blockDim.x + threadIdx.x;
    if (idx >= B_*E_) return;
    int b = idx >> 10, e = idx & (E_ - 1);
    const float* g = g_gates + (long long)b * G4E_;
    float xi = g[e]        + b_ih[e]        + b_hh[e];
    float xf = g[E_   + e] + b_ih[E_   + e] + b_hh[E_   + e];
    float xg = g[2*E_ + e] + b_ih[2*E_ + e] + b_hh[2*E_ + e];
    float xo = g[3*E_ + e] + b_ih[3*E_ + e] + b_hh[3*E_ + e];
    float ig = 1.f / (1.f + __expf(-xi));
    float fg = 1.f / (1.f + __expf(-xf));
    float gg = tanhf(xg);
    float og = 1.f / (1.f + __expf(-xo));
    float c  = fg * g_ctx[idx] + ig * gg;
    float h  = og * tanhf(c);
    h_out[idx] = h;
    c_out[idx] = c;
}

// ---------------------------------------------------------------------------
extern "C" void kernel_launch(void* const* d_in, const int* in_sizes, int n_in,
                              void* d_out, int out_size) {
    const void *p_tgt=0, *p_enc=0, *p_h0=0, *p_pad=0, *p_emb=0, *p_wproj=0,
               *p_wih=0, *p_whh=0, *p_bih=0, *p_bhh=0, *p_bproj=0;
    int seen_be = 0, seen_ve = 0, seen_w = 0, seen_b4 = 0;
    for (int i = 0; i < n_in; i++) {
        long long s = in_sizes[i];
        if      (s == 512)                  p_tgt = d_in[i];
        else if (s == (long long)B_*ML_*E_) p_enc = d_in[i];
        else if (s == (long long)B_*E_)     { if (seen_be++ == 0) p_h0 = d_in[i]; }
        else if (s == B_*ML_)               p_pad = d_in[i];
        else if (s == (long long)V_*E_)     { if (seen_ve++ == 0) p_emb = d_in[i]; else p_wproj = d_in[i]; }
        else if (s == (long long)G4E_*E_)   { if (seen_w++  == 0) p_wih = d_in[i]; else p_whh = d_in[i]; }
        else if (s == G4E_)                 { if (seen_b4++ == 0) p_bih = d_in[i]; else p_bhh = d_in[i]; }
        else if (s == V_)                   p_bproj = d_in[i];
    }

    const int*   tgt    = (const int*)p_tgt;
    const float* enc    = (const float*)p_enc;
    const float* h0     = (const float*)p_h0;
    const float* emb    = (const float*)p_emb;
    const float* w_ih   = (const float*)p_wih;
    const float* w_hh   = (const float*)p_whh;
    const float* b_ih   = (const float*)p_bih;
    const float* b_hh   = (const float*)p_bhh;
    const float* w_proj = (const float*)p_wproj;
    const float* b_proj = (const float*)p_bproj;

    float* out    = (float*)d_out;
    float* logits = out;
    float* h_out  = out + (long long)B_ * V_;
    float* c_out  = h_out + (long long)B_ * E_;

    float *gates;
    cudaGetSymbolAddress((void**)&gates, g_gates);
    __nv_bfloat16 *wp3, *wg3, *ag3, *h3;
    cudaGetSymbolAddress((void**)&wp3, g_wp3);
    cudaGetSymbolAddress((void**)&wg3, g_wg3);
    cudaGetSymbolAddress((void**)&ag3, g_ag3);
    cudaGetSymbolAddress((void**)&h3,  g_h3);

    cudaFuncSetAttribute(gemm_bf16_mma, cudaFuncAttributeMaxDynamicSharedMemorySize, GEMM_SMEM);

    detect_pad_kernel<<<1, 1024>>>((const unsigned char*)p_pad);
    gather_words_kernel<<<(B_*E_ + 255)/256, 256>>>(tgt, emb);
    attn_kernel<<<B_, 256>>>(enc, h0, p_pad);

    {
        long long tot = (long long)NPADV * (E_/4);
        conv_wproj_kernel<<<(unsigned)((tot + 255)/256), 256>>>(w_proj);
        long long tg = (long long)G4E_ * (KG/4);
        conv_wgate_kernel<<<(unsigned)((tg + 255)/256), 256>>>(w_ih, w_hh);
    }
    conv_agate_kernel<<<(B_*(KG/4) + 255)/256, 256>>>();

    // gates GEMM: [512,6144] x [4096,6144]^T -> g_gates
    {
        dim3 grid(G4E_/128, B_/128);
        gemm_bf16_mma<<<grid, 256, GEMM_SMEM>>>(ag3, wg3, gates, nullptr, KG3, G4E_);
    }

    lstm_kernel<<<(B_*E_ + 255)/256, 256>>>(b_ih, b_hh, h_out, c_out);
    conv_h_kernel<<<(B_*(E_/4) + 255)/256, 256>>>(h_out);

    // logits GEMM: [512,3072] x [50048,3072]^T -> logits (+b_proj)
    {
        dim3 grid(NPADV/128, B_/128);
        gemm_bf16_mma<<<grid, 256, GEMM_SMEM>>>(h3, wp3, logits, b_proj, KP3, V_);
    }
}

// round 7
// speedup vs baseline: 2.6863x; 2.6863x over previous
#include <cuda_runtime.h>
#include <cuda_fp16.h>
#include <math.h>
#include <stdint.h>

#define B_    512
#define E_    1024
#define ML_   50
#define V_    50000
#define G4E_  (4*E_)
#define NPADV 50048          // V padded to multiple of 128
#define KP2   (2*E_)         // 2048: logits K after x2 expansion
#define KGB   2048           // gates base K ([words|ctx] vs [w_ih|w_hh])
#define KG2   (2*KGB)        // 4096

// ---------------- scratch (__device__ globals; allocation-free rule) --------
__device__ float g_ctx[B_*E_];
__device__ float g_gates[(long long)B_*G4E_];
__device__ int   g_pad_byte_mode;

__device__ __half g_wp2[(long long)NPADV*KP2];   // [Bhi | Blo]
__device__ __half g_wg2[(long long)G4E_*KG2];    // [Bhi | Blo]
__device__ __half g_ag2[B_*KG2];                 // [Ahi | Ahi]
__device__ __half g_h2[B_*KP2];                  // [Hhi | Hhi]

union H8 { __half h[8]; uint4 u; };

// ---------------- PTX helpers (arch-stable, sm_80-era) ----------------------
__device__ __forceinline__ uint32_t smem_u32(const void* p) {
    uint32_t a;
    asm("{ .reg .u64 t; cvta.to.shared.u64 t, %1; cvt.u32.u64 %0, t; }" : "=r"(a) : "l"(p));
    return a;
}
#define CP_ASYNC16(dst, src) \
    asm volatile("cp.async.cg.shared.global [%0], [%1], 16;" :: "r"(dst), "l"(src) : "memory")
#define CP_COMMIT() asm volatile("cp.async.commit_group;" ::: "memory")
#define CP_WAIT1()  asm volatile("cp.async.wait_group 1;" ::: "memory")
#define CP_WAIT0()  asm volatile("cp.async.wait_group 0;" ::: "memory")

__device__ __forceinline__ void ldsm_x4(uint32_t addr, uint32_t& r0, uint32_t& r1,
                                        uint32_t& r2, uint32_t& r3) {
    asm volatile("ldmatrix.sync.aligned.m8n8.x4.shared.b16 {%0,%1,%2,%3}, [%4];"
                 : "=r"(r0), "=r"(r1), "=r"(r2), "=r"(r3) : "r"(addr));
}
__device__ __forceinline__ void mma16816(float* c, const uint32_t* a, const uint32_t* b) {
    asm volatile("mma.sync.aligned.m16n8k16.row.col.f32.f16.f16.f32 "
                 "{%0,%1,%2,%3}, {%4,%5,%6,%7}, {%8,%9}, {%0,%1,%2,%3};"
                 : "+f"(c[0]), "+f"(c[1]), "+f"(c[2]), "+f"(c[3])
                 : "r"(a[0]), "r"(a[1]), "r"(a[2]), "r"(a[3]), "r"(b[0]), "r"(b[1]));
}
__device__ __forceinline__ uint32_t swz128(uint32_t o) { return o ^ ((o >> 3) & 0x70); }

// ---------------------------------------------------------------------------
// pad dtype detect (robust to bool-as-byte vs int32/float32 0/1)
// ---------------------------------------------------------------------------
__global__ void detect_pad_kernel(const unsigned char* __restrict__ pad) {
    __shared__ int s_gt1, s_off4;
    if (threadIdx.x == 0) { s_gt1 = 0; s_off4 = 0; }
    __syncthreads();
    for (int i = threadIdx.x; i < B_*ML_; i += blockDim.x) {
        unsigned char v = pad[i];
        if (v > 1) atomicOr(&s_gt1, 1);
        if (v != 0 && (i & 3) != 0) atomicOr(&s_off4, 1);
    }
    __syncthreads();
    if (threadIdx.x == 0)
        g_pad_byte_mode = (s_gt1 == 0 && s_off4 != 0) ? 1 : 0;
}

// ---------------------------------------------------------------------------
// Embedding gather -> fp16 A-halves of the gates GEMM directly
// A layout [512 x 4096]: cols [0,1024)=words_hi, [1024,2048)=ctx_hi, then repeat
// ---------------------------------------------------------------------------
__global__ void gather_words_kernel(const int* __restrict__ tgt,
                                    const float* __restrict__ emb) {
    int idx = blockIdx.x * blockDim.x + threadIdx.x;
    if (idx >= B_*E_) return;
    int b = idx >> 10, e = idx & (E_ - 1);
    __half h = __float2half_rn(emb[(long long)tgt[b] * E_ + e]);
    g_ag2[b * KG2 + e]        = h;
    g_ag2[b * KG2 + KGB + e]  = h;
}

// ---------------------------------------------------------------------------
// Attention; writes fp32 ctx (for LSTM) + fp16 ctx into gates-A columns
// ---------------------------------------------------------------------------
__global__ void attn_kernel(const float* __restrict__ enc,
                            const float* __restrict__ h0,
                            const void* __restrict__ pad_raw) {
    int b = blockIdx.x;
    __shared__ float sh_h[E_];
    __shared__ float sh_w[ML_];
    int tid = threadIdx.x;
    for (int i = tid; i < E_; i += 256) sh_h[i] = h0[(long long)b*E_ + i];
    __syncthreads();
    int w = tid >> 5, lane = tid & 31;
    for (int l = w; l < ML_; l += 8) {
        const float* row = enc + ((long long)b*ML_ + l) * E_;
        float s = 0.f;
        for (int e = lane; e < E_; e += 32) s += row[e] * sh_h[e];
        #pragma unroll
        for (int o = 16; o > 0; o >>= 1) s += __shfl_down_sync(0xffffffffu, s, o);
        if (lane == 0) sh_w[l] = s;
    }
    __syncthreads();
    if (tid == 0) {
        int bm = g_pad_byte_mode;
        const unsigned char* p8 = (const unsigned char*)pad_raw;
        const unsigned int*  pw = (const unsigned int*)pad_raw;
        float mx = -1e30f;
        for (int l = 0; l < ML_; l++) mx = fmaxf(mx, sh_w[l]);
        float sum = 0.f;
        for (int l = 0; l < ML_; l++) {
            bool masked = bm ? (p8[b*ML_ + l] != 0) : (pw[b*ML_ + l] != 0u);
            float v = masked ? 0.f : __expf(sh_w[l] - mx);
            sh_w[l] = v; sum += v;
        }
        float inv = 1.f / sum;
        for (int l = 0; l < ML_; l++) sh_w[l] *= inv;
    }
    __syncthreads();
    for (int e = tid; e < E_; e += 256) {
        const float* base = enc + (long long)b*ML_*E_ + e;
        float acc = 0.f;
        #pragma unroll 10
        for (int l = 0; l < ML_; l++) acc += sh_w[l] * base[(long long)l*E_];
        g_ctx[(long long)b*E_ + e] = acc;
        __half h = __float2half_rn(acc);
        g_ag2[b * KG2 + E_ + e]        = h;
        g_ag2[b * KG2 + KGB + E_ + e]  = h;
    }
}

// ---------------------------------------------------------------------------
// fp32 -> fp16 hi/lo split converters (8 elems/thread, 16B stores)
// ---------------------------------------------------------------------------
__global__ void conv_wproj_kernel(const float* __restrict__ src) {
    long long t = (long long)blockIdx.x * blockDim.x + threadIdx.x;
    const long long total = (long long)NPADV * (E_/8);
    if (t >= total) return;
    int row = (int)(t / (E_/8));
    int k0  = (int)(t % (E_/8)) * 8;
    float v[8];
    if (row < V_) {
        const float4 a = *(const float4*)(src + (long long)row*E_ + k0);
        const float4 b = *(const float4*)(src + (long long)row*E_ + k0 + 4);
        v[0]=a.x; v[1]=a.y; v[2]=a.z; v[3]=a.w; v[4]=b.x; v[5]=b.y; v[6]=b.z; v[7]=b.w;
    } else {
        #pragma unroll
        for (int q = 0; q < 8; q++) v[q] = 0.f;
    }
    H8 hi, lo;
    #pragma unroll
    for (int q = 0; q < 8; q++) {
        hi.h[q] = __float2half_rn(v[q]);
        lo.h[q] = __float2half_rn(v[q] - __half2float(hi.h[q]));
    }
    long long o = (long long)row * KP2 + k0;
    *(uint4*)&g_wp2[o]       = hi.u;
    *(uint4*)&g_wp2[o + E_]  = lo.u;
}

__global__ void conv_wgate_kernel(const float* __restrict__ w_ih,
                                  const float* __restrict__ w_hh) {
    long long t = (long long)blockIdx.x * blockDim.x + threadIdx.x;
    const long long total = (long long)G4E_ * (KGB/8);
    if (t >= total) return;
    int row = (int)(t / (KGB/8));
    int k0  = (int)(t % (KGB/8)) * 8;
    const float* s = (k0 < E_) ? (w_ih + (long long)row*E_ + k0)
                               : (w_hh + (long long)row*E_ + (k0 - E_));
    const float4 a = *(const float4*)s;
    const float4 b = *(const float4*)(s + 4);
    float v[8] = {a.x,a.y,a.z,a.w,b.x,b.y,b.z,b.w};
    H8 hi, lo;
    #pragma unroll
    for (int q = 0; q < 8; q++) {
        hi.h[q] = __float2half_rn(v[q]);
        lo.h[q] = __float2half_rn(v[q] - __half2float(hi.h[q]));
    }
    long long o = (long long)row * KG2 + k0;
    *(uint4*)&g_wg2[o]        = hi.u;
    *(uint4*)&g_wg2[o + KGB]  = lo.u;
}

// ---------------------------------------------------------------------------
// fp16 GEMM via mma.sync: C[M,N] = A[M,K2] * B[N,K2]^T (+bias)
// CTA BMx128, K-chunk 64, 3-stage cp.async pipeline, SW128 smem, ldmatrix.
// BM=128: warps 4(m)x2(n), warp tile 32x64. BM=64: warps 2(m)x4(n), 32x32.
// grid.x = m-blocks (fast) so CTAs sharing a B tile run concurrently.
// ---------------------------------------------------------------------------
template<int BM>
__global__ void __launch_bounds__(256, 2) gemm_fp16_mma(
    const __half* __restrict__ A2, const __half* __restrict__ B2,
    float* __restrict__ C, const float* __restrict__ bias,
    int K2, int Nreal)
{
    constexpr int WMW = (BM == 128) ? 4 : 2;       // warps along m
    constexpr int WNW = 8 / WMW;                   // warps along n
    constexpr int WN  = 128 / WNW;                 // n cols per warp
    constexpr int NT  = WN / 8;                    // n mma tiles per warp
    constexpr int ATILE = BM * 128;                // bytes
    constexpr int STAGE = ATILE + 16384;
    constexpr int OPS = (BM + 128) / 32;           // cp.async 16B ops per thread
    constexpr int OPSA = BM * 8;

    extern __shared__ char smem_raw[];
    const uint32_t smem = smem_u32(smem_raw);

    const int tid = threadIdx.x;
    const int wid = tid >> 5, lane = tid & 31;
    const int wm = wid % WMW, wn = wid / WMW;
    const int m0 = blockIdx.x * BM, n0 = blockIdx.y * 128;
    const int nch = K2 >> 6;

    const __half* Abase = A2 + (long long)m0 * K2;
    const __half* Bbase = B2 + (long long)n0 * K2;

    auto issue_stage = [&](int stage, int chunk) {
        int kc = chunk * 64;
        uint32_t sbase = smem + stage * STAGE;
        #pragma unroll
        for (int j = 0; j < OPS; j++) {
            int op = tid + j * 256;
            const __half* src;
            uint32_t dst;
            if (op < OPSA) {
                int row = op >> 3, c = op & 7;
                src = Abase + (long long)row * K2 + kc + c * 8;
                dst = sbase + swz128((uint32_t)(row * 128 + c * 16));
            } else {
                int op2 = op - OPSA;
                int row = op2 >> 3, c = op2 & 7;
                src = Bbase + (long long)row * K2 + kc + c * 8;
                dst = sbase + ATILE + swz128((uint32_t)(row * 128 + c * 16));
            }
            CP_ASYNC16(dst, (const void*)src);
        }
        CP_COMMIT();
    };

    float acc[2][NT][4];
    #pragma unroll
    for (int mt = 0; mt < 2; mt++)
        #pragma unroll
        for (int nt = 0; nt < NT; nt++)
            #pragma unroll
            for (int q = 0; q < 4; q++) acc[mt][nt][q] = 0.f;

    issue_stage(0, 0);
    if (nch > 1) issue_stage(1, 1); else CP_COMMIT();

    const int a_row_in = lane & 15;
    const int a_chunk  = lane >> 4;
    const int b_row_in = (lane & 7) + ((lane & 16) ? 8 : 0);
    const int b_chunk  = (lane >> 3) & 1;

    for (int i = 0; i < nch; i++) {
        CP_WAIT1();
        __syncthreads();
        if (i + 2 < nch) issue_stage((i + 2) % 3, i + 2);
        else CP_COMMIT();

        uint32_t sbase = smem + (i % 3) * STAGE;
        uint32_t As = sbase, Bs = sbase + ATILE;

        #pragma unroll
        for (int ks = 0; ks < 4; ks++) {
            uint32_t a[2][4];
            #pragma unroll
            for (int mt = 0; mt < 2; mt++) {
                int row = wm * 32 + mt * 16 + a_row_in;
                int ch  = ks * 2 + a_chunk;
                uint32_t addr = As + swz128((uint32_t)(row * 128 + ch * 16));
                ldsm_x4(addr, a[mt][0], a[mt][1], a[mt][2], a[mt][3]);
            }
            uint32_t b[NT][2];
            #pragma unroll
            for (int np = 0; np < NT/2; np++) {
                int row = wn * WN + np * 16 + b_row_in;
                int ch  = ks * 2 + b_chunk;
                uint32_t addr = Bs + swz128((uint32_t)(row * 128 + ch * 16));
                ldsm_x4(addr, b[np*2][0], b[np*2][1], b[np*2+1][0], b[np*2+1][1]);
            }
            #pragma unroll
            for (int mt = 0; mt < 2; mt++)
                #pragma unroll
                for (int nt = 0; nt < NT; nt++)
                    mma16816(acc[mt][nt], a[mt], b[nt]);
        }
        __syncthreads();
    }
    CP_WAIT0();

    #pragma unroll
    for (int mt = 0; mt < 2; mt++) {
        int r0g = m0 + wm * 32 + mt * 16 + (lane >> 2);
        #pragma unroll
        for (int nt = 0; nt < NT; nt++) {
            int col = n0 + wn * WN + nt * 8 + (lane & 3) * 2;
            if (col >= Nreal) continue;
            float bx = 0.f, by = 0.f;
            if (bias) { bx = bias[col]; by = bias[col + 1]; }
            float2 v0 = make_float2(acc[mt][nt][0] + bx, acc[mt][nt][1] + by);
            float2 v1 = make_float2(acc[mt][nt][2] + bx, acc[mt][nt][3] + by);
            *(float2*)(C + (long long)r0g * Nreal + col) = v0;
            *(float2*)(C + (long long)(r0g + 8) * Nreal + col) = v1;
        }
    }
}

// ---------------------------------------------------------------------------
// LSTM elementwise; also writes fp16 h duplicated for the logits GEMM A side
// ---------------------------------------------------------------------------
__global__ void lstm_kernel(const float* __restrict__ b_ih,
                            const float* __restrict__ b_hh,
                            float* __restrict__ h_out,
                            float* __restrict__ c_out) {
    int idx = blockIdx.x * blockDim.x + threadIdx.x;
    if (idx >= B_*E_) return;
    int b = idx >> 10, e = idx & (E_ - 1);
    const float* g = g_gates + (long long)b * G4E_;
    float xi = g[e]        + b_ih[e]        + b_hh[e];
    float xf = g[E_   + e] + b_ih[E_   + e] + b_hh[E_   + e];
    float xg = g[2*E_ + e] + b_ih[2*E_ + e] + b_hh[2*E_ + e];
    float xo = g[3*E_ + e] + b_ih[3*E_ + e] + b_hh[3*E_ + e];
    float ig = 1.f / (1.f + __expf(-xi));
    float fg = 1.f / (1.f + __expf(-xf));
    float gg = tanhf(xg);
    float og = 1.f / (1.f + __expf(-xo));
    float c  = fg * g_ctx[idx] + ig * gg;
    float h  = og * tanhf(c);
    h_out[idx] = h;
    c_out[idx] = c;
    __half hh = __float2half_rn(h);
    g_h2[b * KP2 + e]       = hh;
    g_h2[b * KP2 + E_ + e]  = hh;
}

// ---------------------------------------------------------------------------
extern "C" void kernel_launch(void* const* d_in, const int* in_sizes, int n_in,
                              void* d_out, int out_size) {
    const void *p_tgt=0, *p_enc=0, *p_h0=0, *p_pad=0, *p_emb=0, *p_wproj=0,
               *p_wih=0, *p_whh=0, *p_bih=0, *p_bhh=0, *p_bproj=0;
    int seen_be = 0, seen_ve = 0, seen_w = 0, seen_b4 = 0;
    for (int i = 0; i < n_in; i++) {
        long long s = in_sizes[i];
        if      (s == 512)                  p_tgt = d_in[i];
        else if (s == (long long)B_*ML_*E_) p_enc = d_in[i];
        else if (s == (long long)B_*E_)     { if (seen_be++ == 0) p_h0 = d_in[i]; }
        else if (s == B_*ML_)               p_pad = d_in[i];
        else if (s == (long long)V_*E_)     { if (seen_ve++ == 0) p_emb = d_in[i]; else p_wproj = d_in[i]; }
        else if (s == (long long)G4E_*E_)   { if (seen_w++  == 0) p_wih = d_in[i]; else p_whh = d_in[i]; }
        else if (s == G4E_)                 { if (seen_b4++ == 0) p_bih = d_in[i]; else p_bhh = d_in[i]; }
        else if (s == V_)                   p_bproj = d_in[i];
    }

    const int*   tgt    = (const int*)p_tgt;
    const float* enc    = (const float*)p_enc;
    const float* h0     = (const float*)p_h0;
    const float* emb    = (const float*)p_emb;
    const float* w_ih   = (const float*)p_wih;
    const float* w_hh   = (const float*)p_whh;
    const float* b_ih   = (const float*)p_bih;
    const float* b_hh   = (const float*)p_bhh;
    const float* w_proj = (const float*)p_wproj;
    const float* b_proj = (const float*)p_bproj;

    float* out    = (float*)d_out;
    float* logits = out;
    float* h_out  = out + (long long)B_ * V_;
    float* c_out  = h_out + (long long)B_ * E_;

    float *gates;
    cudaGetSymbolAddress((void**)&gates, g_gates);
    __half *wp2, *wg2, *ag2, *h2;
    cudaGetSymbolAddress((void**)&wp2, g_wp2);
    cudaGetSymbolAddress((void**)&wg2, g_wg2);
    cudaGetSymbolAddress((void**)&ag2, g_ag2);
    cudaGetSymbolAddress((void**)&h2,  g_h2);

    const int SMEM128 = 3 * (128*128 + 16384);   // 96 KB
    const int SMEM64  = 3 * (64*128 + 16384);    // 72 KB
    cudaFuncSetAttribute(gemm_fp16_mma<128>, cudaFuncAttributeMaxDynamicSharedMemorySize, SMEM128);
    cudaFuncSetAttribute(gemm_fp16_mma<64>,  cudaFuncAttributeMaxDynamicSharedMemorySize, SMEM64);

    detect_pad_kernel<<<1, 1024>>>((const unsigned char*)p_pad);
    gather_words_kernel<<<(B_*E_ + 255)/256, 256>>>(tgt, emb);
    attn_kernel<<<B_, 256>>>(enc, h0, p_pad);

    {
        long long tg = (long long)G4E_ * (KGB/8);
        conv_wgate_kernel<<<(unsigned)((tg + 255)/256), 256>>>(w_ih, w_hh);
    }

    // gates GEMM: [512,4096] x [4096,4096]^T -> g_gates  (BM=64 -> 256 CTAs)
    {
        dim3 grid(B_/64, G4E_/128);
        gemm_fp16_mma<64><<<grid, 256, SMEM64>>>(ag2, wg2, gates, nullptr, KG2, G4E_);
    }

    lstm_kernel<<<(B_*E_ + 255)/256, 256>>>(b_ih, b_hh, h_out, c_out);

    {
        long long tot = (long long)NPADV * (E_/8);
        conv_wproj_kernel<<<(unsigned)((tot + 255)/256), 256>>>(w_proj);
    }

    // logits GEMM: [512,2048] x [50048,2048]^T -> logits (+b_proj)
    {
        dim3 grid(B_/128, NPADV/128);
        gemm_fp16_mma<128><<<grid, 256, SMEM128>>>(h2, wp2, logits, b_proj, KP2, V_);
    }
}